// round 3
// baseline (speedup 1.0000x reference)
#include <cuda_runtime.h>
#include <math.h>

#define BATCH    8192
#define DLAT     512
#define NCB      2
#define KCODES   8192
#define DSUB     256

#define BM 128
#define BN 128
#define BK 16

// Scratch (no allocations allowed)
__device__ unsigned long long g_packed[BATCH * NCB];   // (sortable_u<<32)|k
__device__ int    g_counts[NCB * KCODES];
__device__ float  g_zsq[BATCH * NCB];
__device__ double g_sse;

// ---------------------------------------------------------------------------
__global__ void init_kernel() {
    int i = blockIdx.x * blockDim.x + threadIdx.x;
    if (i < BATCH * NCB)  g_packed[i] = 0xFFFFFFFFFFFFFFFFull;
    if (i < NCB * KCODES) g_counts[i] = 0;
    if (i == 0)           g_sse = 0.0;
}

// ---------------------------------------------------------------------------
// z_sq[b,n] = sum_d z[b, n*256+d]^2. (Ranking is provably invariant to
// ulp-scale error here; only the binade and boundary-straddle rows matter.)
__global__ void zsq_kernel(const float* __restrict__ z) {
    int w    = blockIdx.x * (blockDim.x >> 5) + (threadIdx.x >> 5);  // 0..16383
    int lane = threadIdx.x & 31;
    const float* row = z + (size_t)w * DSUB;   // (b,n) row: w = b*2+n
    float s = 0.f;
#pragma unroll
    for (int t = 0; t < DSUB / 32; t++) {
        float v  = row[lane + 32 * t];
        float sq = __fmul_rn(v, v);
        s = __fadd_rn(s, sq);
    }
#pragma unroll
    for (int o = 16; o; o >>= 1)
        s = __fadd_rn(s, __shfl_down_sync(0xffffffffu, s, o));
    if (lane == 0) g_zsq[w] = s;
}

// ---------------------------------------------------------------------------
// Fused exact-fp32 GEMM (c = Z_n * E_n^T, single accumulator, FMA, strictly
// ascending k) + per-row argmin of u = RN(z_sq - 2*c), ties -> lowest k.
// (e_sq provably never affects the fp32-rounded distance; dropped.)
__global__ __launch_bounds__(256, 2)
void gemm_argmin_kernel(const float* __restrict__ z, const float* __restrict__ emb) {
    __shared__ float As[2][BK][BM];
    __shared__ float Bs[2][BK][BN];

    const int n  = blockIdx.z;
    const int bm = blockIdx.y;
    const int bn = blockIdx.x;
    const int tid = threadIdx.x;
    const int tx = tid & 15;     // col group (k-codes)
    const int ty = tid >> 4;     // row group (batch)

    const float* Ag = z   + (size_t)(bm * BM) * DLAT + n * DSUB;
    const float* Bg = emb + (size_t)n * KCODES * DSUB + (size_t)(bn * BN) * DSUB;

    float acc[8][8];
#pragma unroll
    for (int i = 0; i < 8; i++)
#pragma unroll
        for (int j = 0; j < 8; j++) acc[i][j] = 0.f;

    auto loadA = [&](int buf, int kb) {
#pragma unroll
        for (int u = 0; u < 2; u++) {
            int s = tid + u * 256;
            int r = s & 127;
            int c = (s >> 7) * 4;
            float4 v = *(const float4*)(Ag + (size_t)r * DLAT + kb + c);
            As[buf][c + 0][r] = v.x; As[buf][c + 1][r] = v.y;
            As[buf][c + 2][r] = v.z; As[buf][c + 3][r] = v.w;
        }
    };
    auto loadB = [&](int buf, int kb) {
#pragma unroll
        for (int u = 0; u < 2; u++) {
            int s = tid + u * 256;
            int r = s & 127;
            int c = (s >> 7) * 4;
            float4 v = *(const float4*)(Bg + (size_t)r * DSUB + kb + c);
            Bs[buf][c + 0][r] = v.x; Bs[buf][c + 1][r] = v.y;
            Bs[buf][c + 2][r] = v.z; Bs[buf][c + 3][r] = v.w;
        }
    };

    loadA(0, 0);
    loadB(0, 0);
    __syncthreads();

    for (int kb = 0; kb < DSUB; kb += BK) {
        int cur = (kb / BK) & 1;
        int nxt = cur ^ 1;
        if (kb + BK < DSUB) { loadA(nxt, kb + BK); loadB(nxt, kb + BK); }

#pragma unroll
        for (int kk = 0; kk < BK; kk++) {
            float a[8], b[8];
            *(float4*)(a)     = *(const float4*)&As[cur][kk][ty * 8];
            *(float4*)(a + 4) = *(const float4*)&As[cur][kk][ty * 8 + 4];
            *(float4*)(b)     = *(const float4*)&Bs[cur][kk][tx * 8];
            *(float4*)(b + 4) = *(const float4*)&Bs[cur][kk][tx * 8 + 4];
#pragma unroll
            for (int i = 0; i < 8; i++)
#pragma unroll
                for (int j = 0; j < 8; j++)
                    acc[i][j] = __fmaf_rn(a[i], b[j], acc[i][j]);
        }
        __syncthreads();
    }

    // Epilogue: u = RN(zsq - 2*c); argmin with lowest-k tie-break
#pragma unroll
    for (int i = 0; i < 8; i++) {
        int b = bm * BM + ty * 8 + i;
        float zsq = g_zsq[(size_t)b * NCB + n];
        unsigned long long key = 0xFFFFFFFFFFFFFFFFull;
#pragma unroll
        for (int j = 0; j < 8; j++) {
            float u = __fmaf_rn(-2.0f, acc[i][j], zsq);   // == RN(zsq - 2c), 2c exact
            unsigned ub = __float_as_uint(u);
            ub = (ub & 0x80000000u) ? ~ub : (ub | 0x80000000u);   // sortable
            unsigned long long cand =
                ((unsigned long long)ub << 32) | (unsigned)(bn * BN + tx * 8 + j);
            if (cand < key) key = cand;
        }
#pragma unroll
        for (int o = 1; o < 16; o <<= 1) {
            unsigned long long other = __shfl_xor_sync(0xffffffffu, key, o);
            if (other < key) key = other;
        }
        if (tx == 0) atomicMin(&g_packed[(size_t)b * NCB + n], key);
    }
}

// ---------------------------------------------------------------------------
// Gather quantized vectors with straight-through rounding semantics:
// out = RN(z + RN(z_q - z))   (NOT z_q — the two roundings matter, ~7e-4).
// Also write indices, accumulate commitment SSE + usage counts.
__global__ void gather_kernel(const float* __restrict__ z,
                              const float* __restrict__ emb,
                              float* __restrict__ out) {
    int w    = blockIdx.x * (blockDim.x >> 5) + (threadIdx.x >> 5);  // 0..16383
    int lane = threadIdx.x & 31;
    int b = w >> 1;
    int n = w & 1;

    unsigned long long key = g_packed[w];          // w == b*NCB + n
    int idx = (int)(key & 0xFFFFFFFFull);

    if (lane == 0) {
        out[(size_t)BATCH * DLAT + w] = (float)idx;      // indices block
        atomicAdd(&g_counts[n * KCODES + idx], 1);
    }

    const float* e  = emb + ((size_t)n * KCODES + idx) * DSUB;
    const float* zp = z   + (size_t)b * DLAT + n * DSUB;
    float*       op = out + (size_t)b * DLAT + n * DSUB;

    float s = 0.f;
#pragma unroll
    for (int t = 0; t < DSUB / 32; t++) {
        float ev = e[lane + 32 * t];
        float zv = zp[lane + 32 * t];
        float r  = __fsub_rn(ev, zv);              // RN(z_q - z)
        op[lane + 32 * t] = __fadd_rn(zv, r);      // RN(z + r)  (straight-through)
        float d = __fsub_rn(zv, ev);               // commitment uses (z - z_q)
        s = __fmaf_rn(d, d, s);
    }
#pragma unroll
    for (int o = 16; o; o >>= 1) s += __shfl_down_sync(0xffffffffu, s, o);
    if (lane == 0) atomicAdd(&g_sse, (double)s);
}

// ---------------------------------------------------------------------------
__global__ void final_kernel(float* __restrict__ out) {
    __shared__ float red[256];
    int tid = threadIdx.x;
    float s = 0.f;
    for (int k = tid; k < KCODES; k += 256) {
        float p = (float)(g_counts[k] + g_counts[KCODES + k]) /
                  (float)(NCB * BATCH);
        s += p * logf(p + 1e-10f);
    }
    red[tid] = s;
    __syncthreads();
    for (int o = 128; o; o >>= 1) {
        if (tid < o) red[tid] += red[tid + o];
        __syncthreads();
    }
    if (tid == 0) {
        size_t off = (size_t)BATCH * DLAT + (size_t)BATCH * NCB;
        out[off + 0] = (float)(0.25 * (g_sse / (double)((size_t)BATCH * DLAT)));
        out[off + 1] = 0.0f;                      // codebook_loss (EMA/eval)
        out[off + 2] = expf(-red[0]);             // perplexity
    }
}

// ---------------------------------------------------------------------------
extern "C" void kernel_launch(void* const* d_in, const int* in_sizes, int n_in,
                              void* d_out, int out_size) {
    const float* z   = (const float*)d_in[0];   // [8192, 512]
    const float* emb = (const float*)d_in[1];   // [2, 8192, 256]
    float* out = (float*)d_out;

    init_kernel<<<64, 256>>>();
    zsq_kernel<<<(BATCH * NCB) / 8, 256>>>(z);

    dim3 grid(KCODES / BN, BATCH / BM, NCB);
    gemm_argmin_kernel<<<grid, 256>>>(z, emb);

    gather_kernel<<<(BATCH * NCB) / 8, 256>>>(z, emb, out);
    final_kernel<<<1, 256>>>(out);
}